// round 6
// baseline (speedup 1.0000x reference)
#include <cuda_runtime.h>
#include <cuda_bf16.h>

#define LT_W 0.5f
#define LIN_W 0.1f
#define THREADS 256
#define U 4
#define CTAS_PER_SM 6
#define NUM_SMS 148
#define PER_CTA_F4 (THREADS * U)   // 1024 float4 = 16 KiB per iteration per CTA

__device__ __forceinline__ float4 sel4(float4 v) {
    v.x = (v.x < LT_W) ? v.x * LIN_W : v.x;
    v.y = (v.y < LT_W) ? v.y * LIN_W : v.y;
    v.z = (v.z < LT_W) ? v.z * LIN_W : v.z;
    v.w = (v.w < LT_W) ? v.w * LIN_W : v.w;
    return v;
}

// Persistent single-wave kernel, software-pipelined grid-stride loop.
// Next iteration's loads are issued BEFORE current iteration's stores,
// keeping ~8 LDG.128 in flight per thread across the whole sweep.
__global__ void __launch_bounds__(THREADS, CTAS_PER_SM) apply_lt_lin_persist(
    const float4* __restrict__ x, float4* __restrict__ out, int n4)
{
    const int stride = gridDim.x * PER_CTA_F4;
    int i = blockIdx.x * PER_CTA_F4 + threadIdx.x;

    float4 v[U];
    #pragma unroll
    for (int k = 0; k < U; k++) {
        int idx = i + k * THREADS;
        if (idx < n4) v[k] = __ldcs(&x[idx]);
    }

    while (i < n4) {
        int inext = i + stride;

        // Prefetch next chunk (guarded) -- overlaps with current stores
        float4 w[U];
        #pragma unroll
        for (int k = 0; k < U; k++) {
            int idx = inext + k * THREADS;
            if (idx < n4) w[k] = __ldcs(&x[idx]);
        }

        // Transform + store current chunk
        #pragma unroll
        for (int k = 0; k < U; k++) {
            int idx = i + k * THREADS;
            if (idx < n4) __stcs(&out[idx], sel4(v[k]));
        }

        #pragma unroll
        for (int k = 0; k < U; k++) v[k] = w[k];
        i = inext;
    }
}

// Scalar tail for n % 4 != 0 (not hit for this shape)
__global__ void apply_lt_lin_tail(
    const float* __restrict__ x, float* __restrict__ out, int start, int n)
{
    int i = start + blockIdx.x * blockDim.x + threadIdx.x;
    if (i < n) {
        float v = x[i];
        out[i] = (v < LT_W) ? v * LIN_W : v;
    }
}

extern "C" void kernel_launch(void* const* d_in, const int* in_sizes, int n_in,
                              void* d_out, int out_size)
{
    const float* x = (const float*)d_in[0];
    float* out = (float*)d_out;
    int n = in_sizes[0];

    int n4 = n / 4;
    if (n4 > 0) {
        int full_grid = NUM_SMS * CTAS_PER_SM;                    // exactly one wave
        int needed = (n4 + PER_CTA_F4 - 1) / PER_CTA_F4;
        int blocks = needed < full_grid ? needed : full_grid;
        apply_lt_lin_persist<<<blocks, THREADS>>>(
            (const float4*)x, (float4*)out, n4);
    }
    int rem = n - n4 * 4;
    if (rem > 0) {
        apply_lt_lin_tail<<<1, 128>>>(x, out, n4 * 4, n);
    }
}

// round 7
// speedup vs baseline: 1.1475x; 1.1475x over previous
#include <cuda_runtime.h>
#include <cuda_bf16.h>

#define LT_W 0.5f
#define LIN_W 0.1f
#define THREADS 512
#define V8_PER_THREAD 2
// floats per CTA = 512 threads * 8 floats * 2 = 8192 (32 KiB)
#define PER_CTA_FLOATS (THREADS * 8 * V8_PER_THREAD)

__device__ __forceinline__ void ld_v8(const float* p, float* r) {
    unsigned u0,u1,u2,u3,u4,u5,u6,u7;
    asm volatile("ld.global.nc.v8.b32 {%0,%1,%2,%3,%4,%5,%6,%7}, [%8];"
        : "=r"(u0),"=r"(u1),"=r"(u2),"=r"(u3),
          "=r"(u4),"=r"(u5),"=r"(u6),"=r"(u7)
        : "l"(p));
    r[0]=__uint_as_float(u0); r[1]=__uint_as_float(u1);
    r[2]=__uint_as_float(u2); r[3]=__uint_as_float(u3);
    r[4]=__uint_as_float(u4); r[5]=__uint_as_float(u5);
    r[6]=__uint_as_float(u6); r[7]=__uint_as_float(u7);
}

__device__ __forceinline__ void st_v8(float* p, const float* r) {
    asm volatile("st.global.v8.b32 [%0], {%1,%2,%3,%4,%5,%6,%7,%8};"
        :: "l"(p),
           "r"(__float_as_uint(r[0])), "r"(__float_as_uint(r[1])),
           "r"(__float_as_uint(r[2])), "r"(__float_as_uint(r[3])),
           "r"(__float_as_uint(r[4])), "r"(__float_as_uint(r[5])),
           "r"(__float_as_uint(r[6])), "r"(__float_as_uint(r[7]))
        : "memory");
}

__device__ __forceinline__ float sel1(float v) {
    return (v < LT_W) ? v * LIN_W : v;
}

// Fast path: exact cover, 2 x 256-bit accesses per thread, no bounds checks.
__global__ void __launch_bounds__(THREADS) apply_lt_lin_v8(
    const float* __restrict__ x, float* __restrict__ out)
{
    int base = blockIdx.x * PER_CTA_FLOATS + threadIdx.x * 8;

    float a[8], b[8];
    ld_v8(x + base, a);
    ld_v8(x + base + THREADS * 8, b);

    #pragma unroll
    for (int k = 0; k < 8; k++) a[k] = sel1(a[k]);
    #pragma unroll
    for (int k = 0; k < 8; k++) b[k] = sel1(b[k]);

    st_v8(out + base, a);
    st_v8(out + base + THREADS * 8, b);
}

// Guarded float4 path for remainder float4's (not hit for this shape)
__global__ void __launch_bounds__(256) apply_lt_lin_guarded(
    const float4* __restrict__ x, float4* __restrict__ out, int start4, int n4)
{
    int i = start4 + blockIdx.x * 256 + threadIdx.x;
    if (i < n4) {
        float4 v = x[i];
        v.x = sel1(v.x); v.y = sel1(v.y); v.z = sel1(v.z); v.w = sel1(v.w);
        out[i] = v;
    }
}

// Scalar tail for n % 4 != 0
__global__ void apply_lt_lin_tail(
    const float* __restrict__ x, float* __restrict__ out, int start, int n)
{
    int i = start + blockIdx.x * blockDim.x + threadIdx.x;
    if (i < n) out[i] = sel1(x[i]);
}

extern "C" void kernel_launch(void* const* d_in, const int* in_sizes, int n_in,
                              void* d_out, int out_size)
{
    const float* x = (const float*)d_in[0];
    float* out = (float*)d_out;
    int n = in_sizes[0];

    int exact_blocks = n / PER_CTA_FLOATS;
    if (exact_blocks > 0) {
        apply_lt_lin_v8<<<exact_blocks, THREADS>>>(x, out);
    }
    int done = exact_blocks * PER_CTA_FLOATS;

    int n4 = n / 4;
    int done4 = done / 4;
    int rem4 = n4 - done4;
    if (rem4 > 0) {
        int blocks = (rem4 + 255) / 256;
        apply_lt_lin_guarded<<<blocks, 256>>>(
            (const float4*)x, (float4*)out, done4, n4);
    }
    int rem = n - n4 * 4;
    if (rem > 0) {
        apply_lt_lin_tail<<<1, 128>>>(x, out, n4 * 4, n);
    }
}

// round 8
// speedup vs baseline: 1.1480x; 1.0004x over previous
#include <cuda_runtime.h>
#include <cuda_bf16.h>

#define LT_W 0.5f
#define LIN_W 0.1f
#define THREADS 256
#define U 4
#define PER_CTA_F4 (THREADS * U)          // 1024 float4 per CTA
#define PER_CTA_FLOATS (PER_CTA_F4 * 4)   // 4096 floats per CTA

__device__ __forceinline__ float sel1(float v) {
    return (v < LT_W) ? v * LIN_W : v;
}

__device__ __forceinline__ float4 sel4(float4 v) {
    v.x = sel1(v.x); v.y = sel1(v.y); v.z = sel1(v.z); v.w = sel1(v.w);
    return v;
}

// Fast path: exact cover, 4 front-batched unguarded LDG.128 per thread.
// 64 B/thread, ~24 regs -> full occupancy; streaming evict-first hints.
__global__ void __launch_bounds__(THREADS) apply_lt_lin_v4x4_exact(
    const float4* __restrict__ x, float4* __restrict__ out)
{
    int base = blockIdx.x * PER_CTA_F4 + threadIdx.x;

    float4 v[U];
    #pragma unroll
    for (int k = 0; k < U; k++)
        v[k] = __ldcs(&x[base + k * THREADS]);

    #pragma unroll
    for (int k = 0; k < U; k++)
        __stcs(&out[base + k * THREADS], sel4(v[k]));
}

// Guarded float4 path for remainder (never launched for this shape)
__global__ void __launch_bounds__(THREADS) apply_lt_lin_guarded(
    const float4* __restrict__ x, float4* __restrict__ out, int start4, int n4)
{
    int i = start4 + blockIdx.x * THREADS + threadIdx.x;
    if (i < n4) __stcs(&out[i], sel4(__ldcs(&x[i])));
}

// Scalar tail for n % 4 != 0
__global__ void apply_lt_lin_tail(
    const float* __restrict__ x, float* __restrict__ out, int start, int n)
{
    int i = start + blockIdx.x * blockDim.x + threadIdx.x;
    if (i < n) out[i] = sel1(x[i]);
}

extern "C" void kernel_launch(void* const* d_in, const int* in_sizes, int n_in,
                              void* d_out, int out_size)
{
    const float* x = (const float*)d_in[0];
    float* out = (float*)d_out;
    int n = in_sizes[0];

    int exact_blocks = n / PER_CTA_FLOATS;
    if (exact_blocks > 0) {
        apply_lt_lin_v4x4_exact<<<exact_blocks, THREADS>>>(
            (const float4*)x, (float4*)out);
    }
    int done = exact_blocks * PER_CTA_FLOATS;

    int n4 = n / 4;
    int done4 = done / 4;
    int rem4 = n4 - done4;
    if (rem4 > 0) {
        int blocks = (rem4 + THREADS - 1) / THREADS;
        apply_lt_lin_guarded<<<blocks, THREADS>>>(
            (const float4*)x, (float4*)out, done4, n4);
    }
    int rem = n - n4 * 4;
    if (rem > 0) {
        apply_lt_lin_tail<<<1, 128>>>(x, out, n4 * 4, n);
    }
}